// round 2
// baseline (speedup 1.0000x reference)
#include <cuda_runtime.h>
#include <cuda_bf16.h>
#include <cstdint>

// Problem constants
#define TT 4096      // B*S tokens
#define HH 1024      // hidden
#define II 2048      // intermediate
#define EE 8         // experts
// GEMM tiling
#define BM 64
#define BN 64
#define BK 16

// ---------------- scratch (device globals: no allocation allowed) ----------
__device__ float g_F[(size_t)2 * TT * II];      // 8192 x 2048 fused activations (64 MB)
__device__ float g_slot[(size_t)2 * TT * HH];   // 8192 x 1024 per-(token,k) outputs (32 MB)
__device__ int   g_cnt[EE];
__device__ int   g_rows[EE * TT];               // stores r = t*2 + k
__device__ float g_wts[EE * TT];

// ---------------- helpers ----------------
__device__ __forceinline__ unsigned f2tf(float f) {
    unsigned u;
    asm("cvt.rna.tf32.f32 %0, %1;" : "=r"(u) : "f"(f));
    return u;
}

__device__ __forceinline__ void mma_tf32(float c[4], const unsigned a[4], const unsigned b[2]) {
    asm volatile(
        "mma.sync.aligned.m16n8k8.row.col.f32.tf32.tf32.f32 "
        "{%0,%1,%2,%3}, {%4,%5,%6,%7}, {%8,%9}, {%0,%1,%2,%3};\n"
        : "+f"(c[0]), "+f"(c[1]), "+f"(c[2]), "+f"(c[3])
        : "r"(a[0]), "r"(a[1]), "r"(a[2]), "r"(a[3]), "r"(b[0]), "r"(b[1]));
}

// ---------------- 0: zero expert counters ----------------
__global__ void zero_cnt_kernel() {
    if (threadIdx.x < EE) g_cnt[threadIdx.x] = 0;
}

// ---------------- 1: router (1 warp per token) ----------------
__global__ void router_kernel(const float* __restrict__ x, const float* __restrict__ Wg) {
    int t = (blockIdx.x * blockDim.x + threadIdx.x) >> 5;
    int lane = threadIdx.x & 31;
    if (t >= TT) return;
    const float* xr = x + (size_t)t * HH;
    float acc[EE];
#pragma unroll
    for (int e = 0; e < EE; e++) acc[e] = 0.f;
    for (int h = lane; h < HH; h += 32) {
        float xv = xr[h];
        const float4* wg = reinterpret_cast<const float4*>(Wg + h * EE);
        float4 w0 = wg[0], w1 = wg[1];
        acc[0] += xv * w0.x; acc[1] += xv * w0.y; acc[2] += xv * w0.z; acc[3] += xv * w0.w;
        acc[4] += xv * w1.x; acc[5] += xv * w1.y; acc[6] += xv * w1.z; acc[7] += xv * w1.w;
    }
#pragma unroll
    for (int off = 16; off > 0; off >>= 1) {
#pragma unroll
        for (int e = 0; e < EE; e++)
            acc[e] += __shfl_xor_sync(0xffffffffu, acc[e], off);
    }
    if (lane == 0) {
        float m = acc[0];
#pragma unroll
        for (int e = 1; e < EE; e++) m = fmaxf(m, acc[e]);
        float p[EE];
        float s = 0.f;
#pragma unroll
        for (int e = 0; e < EE; e++) { p[e] = __expf(acc[e] - m); s += p[e]; }
        float inv = 1.f / s;
        // top-2 (strict > keeps lowest index on ties, matching jax.lax.top_k)
        int i0 = 0;
#pragma unroll
        for (int e = 1; e < EE; e++) if (p[e] > p[i0]) i0 = e;
        int i1 = -1;
#pragma unroll
        for (int e = 0; e < EE; e++) {
            if (e == i0) continue;
            if (i1 < 0 || p[e] > p[i1]) i1 = e;
        }
        float s0 = p[i0] * inv, s1 = p[i1] * inv;
        float denom = s0 + s1 + 1e-8f;
        float w0 = s0 / denom, w1 = s1 / denom;
        int pos0 = atomicAdd(&g_cnt[i0], 1);
        g_rows[i0 * TT + pos0] = t * 2 + 0;
        g_wts[i0 * TT + pos0] = w0;
        int pos1 = atomicAdd(&g_cnt[i1], 1);
        g_rows[i1 * TT + pos1] = t * 2 + 1;
        g_wts[i1 * TT + pos1] = w1;
    }
}

// ---------------- 2: grouped GEMM1: F = SiLU(X@W11) * (X@W12) ----------------
// grid: (II/BN, TT/BM, EE), 128 threads
__global__ __launch_bounds__(128) void gemm1_kernel(
    const float* __restrict__ x,
    const float* __restrict__ W11,
    const float* __restrict__ W12)
{
    int e = blockIdx.z;
    int cnt = g_cnt[e];
    int m0 = blockIdx.y * BM;
    if (m0 >= cnt) return;
    int n0 = blockIdx.x * BN;

    __shared__ unsigned Xs[BM][20];
    __shared__ unsigned W1s[BK][72];
    __shared__ unsigned W2s[BK][72];
    __shared__ int rloc[BM];

    int tid = threadIdx.x;
    int lane = tid & 31;
    int warp = tid >> 5;
    int wm = (warp >> 1) * 32;
    int wn = (warp & 1) * 32;

    if (tid < BM) {
        int mi = m0 + tid;
        if (mi >= cnt) mi = cnt - 1;   // clamp; stores are guarded
        rloc[tid] = g_rows[e * TT + mi];
    }
    __syncthreads();

    float cG[2][4][4], cV[2][4][4];
#pragma unroll
    for (int a = 0; a < 2; a++)
#pragma unroll
        for (int b = 0; b < 4; b++)
#pragma unroll
            for (int c = 0; c < 4; c++) { cG[a][b][c] = 0.f; cV[a][b][c] = 0.f; }

    const float* W11base = W11 + (size_t)e * HH * II + n0;
    const float* W12base = W12 + (size_t)e * HH * II + n0;

    for (int kk = 0; kk < HH; kk += BK) {
        // X tile: 64 rows x 16 cols (4 x float4 per row)
#pragma unroll
        for (int p = 0; p < 2; p++) {
            int row = (tid >> 2) + p * 32;
            int cg = (tid & 3) * 4;
            int tok = rloc[row] >> 1;
            float4 v = *reinterpret_cast<const float4*>(x + (size_t)tok * HH + kk + cg);
            Xs[row][cg + 0] = f2tf(v.x); Xs[row][cg + 1] = f2tf(v.y);
            Xs[row][cg + 2] = f2tf(v.z); Xs[row][cg + 3] = f2tf(v.w);
        }
        // W tiles: 16 rows x 64 cols (16 x float4 per row)
#pragma unroll
        for (int p = 0; p < 2; p++) {
            int row = (tid >> 4) + p * 8;
            int cg = (tid & 15) * 4;
            size_t off = (size_t)(kk + row) * II + cg;
            float4 v1 = *reinterpret_cast<const float4*>(W11base + off);
            W1s[row][cg + 0] = f2tf(v1.x); W1s[row][cg + 1] = f2tf(v1.y);
            W1s[row][cg + 2] = f2tf(v1.z); W1s[row][cg + 3] = f2tf(v1.w);
            float4 v2 = *reinterpret_cast<const float4*>(W12base + off);
            W2s[row][cg + 0] = f2tf(v2.x); W2s[row][cg + 1] = f2tf(v2.y);
            W2s[row][cg + 2] = f2tf(v2.z); W2s[row][cg + 3] = f2tf(v2.w);
        }
        __syncthreads();

#pragma unroll
        for (int ks = 0; ks < BK; ks += 8) {
            unsigned a[2][4];
#pragma unroll
            for (int mt = 0; mt < 2; mt++) {
                int r = wm + mt * 16 + (lane >> 2);
                int c = ks + (lane & 3);
                a[mt][0] = Xs[r][c];
                a[mt][1] = Xs[r + 8][c];
                a[mt][2] = Xs[r][c + 4];
                a[mt][3] = Xs[r + 8][c + 4];
            }
#pragma unroll
            for (int nt = 0; nt < 4; nt++) {
                int nc = wn + nt * 8 + (lane >> 2);
                int kr = ks + (lane & 3);
                unsigned b1[2] = { W1s[kr][nc], W1s[kr + 4][nc] };
                unsigned b2[2] = { W2s[kr][nc], W2s[kr + 4][nc] };
                mma_tf32(cG[0][nt], a[0], b1);
                mma_tf32(cG[1][nt], a[1], b1);
                mma_tf32(cV[0][nt], a[0], b2);
                mma_tf32(cV[1][nt], a[1], b2);
            }
        }
        __syncthreads();
    }

    // epilogue: f = g * sigmoid(g) * v, scattered to g_F[r]
#pragma unroll
    for (int mt = 0; mt < 2; mt++) {
#pragma unroll
        for (int half = 0; half < 2; half++) {
            int r = wm + mt * 16 + (lane >> 2) + half * 8;
            if (m0 + r < cnt) {
                int rg = rloc[r];
                float* dst = g_F + (size_t)rg * II + n0 + wn;
#pragma unroll
                for (int nt = 0; nt < 4; nt++) {
                    float g0 = cG[mt][nt][half * 2 + 0], g1 = cG[mt][nt][half * 2 + 1];
                    float v0 = cV[mt][nt][half * 2 + 0], v1 = cV[mt][nt][half * 2 + 1];
                    float f0 = g0 * v0 / (1.f + __expf(-g0));
                    float f1 = g1 * v1 / (1.f + __expf(-g1));
                    int c = nt * 8 + (lane & 3) * 2;
                    *reinterpret_cast<float2*>(dst + c) = make_float2(f0, f1);
                }
            }
        }
    }
}

// ---------------- 3: grouped GEMM2: O[r] = w[r] * (F[r] @ W2[e]) ----------------
// grid: (HH/BN, TT/BM, EE), 128 threads
__global__ __launch_bounds__(128) void gemm2_kernel(const float* __restrict__ W2)
{
    int e = blockIdx.z;
    int cnt = g_cnt[e];
    int m0 = blockIdx.y * BM;
    if (m0 >= cnt) return;
    int n0 = blockIdx.x * BN;

    __shared__ unsigned As[BM][20];
    __shared__ unsigned Bs[BK][72];
    __shared__ int rloc[BM];
    __shared__ float wloc[BM];

    int tid = threadIdx.x;
    int lane = tid & 31;
    int warp = tid >> 5;
    int wm = (warp >> 1) * 32;
    int wn = (warp & 1) * 32;

    if (tid < BM) {
        int mi = m0 + tid;
        if (mi >= cnt) mi = cnt - 1;
        rloc[tid] = g_rows[e * TT + mi];
        wloc[tid] = g_wts[e * TT + mi];
    }
    __syncthreads();

    float cO[2][4][4];
#pragma unroll
    for (int a = 0; a < 2; a++)
#pragma unroll
        for (int b = 0; b < 4; b++)
#pragma unroll
            for (int c = 0; c < 4; c++) cO[a][b][c] = 0.f;

    const float* Bbase = W2 + (size_t)e * II * HH + n0;

    for (int kk = 0; kk < II; kk += BK) {
        // A tile: 64 rows x 16 cols from g_F (gathered)
#pragma unroll
        for (int p = 0; p < 2; p++) {
            int row = (tid >> 2) + p * 32;
            int cg = (tid & 3) * 4;
            int rg = rloc[row];
            float4 v = *reinterpret_cast<const float4*>(g_F + (size_t)rg * II + kk + cg);
            As[row][cg + 0] = f2tf(v.x); As[row][cg + 1] = f2tf(v.y);
            As[row][cg + 2] = f2tf(v.z); As[row][cg + 3] = f2tf(v.w);
        }
        // B tile: 16 rows x 64 cols from W2[e] (row stride HH)
#pragma unroll
        for (int p = 0; p < 2; p++) {
            int row = (tid >> 4) + p * 8;
            int cg = (tid & 15) * 4;
            size_t off = (size_t)(kk + row) * HH + cg;
            float4 v1 = *reinterpret_cast<const float4*>(Bbase + off);
            Bs[row][cg + 0] = f2tf(v1.x); Bs[row][cg + 1] = f2tf(v1.y);
            Bs[row][cg + 2] = f2tf(v1.z); Bs[row][cg + 3] = f2tf(v1.w);
        }
        __syncthreads();

#pragma unroll
        for (int ks = 0; ks < BK; ks += 8) {
            unsigned a[2][4];
#pragma unroll
            for (int mt = 0; mt < 2; mt++) {
                int r = wm + mt * 16 + (lane >> 2);
                int c = ks + (lane & 3);
                a[mt][0] = As[r][c];
                a[mt][1] = As[r + 8][c];
                a[mt][2] = As[r][c + 4];
                a[mt][3] = As[r + 8][c + 4];
            }
#pragma unroll
            for (int nt = 0; nt < 4; nt++) {
                int nc = wn + nt * 8 + (lane >> 2);
                int kr = ks + (lane & 3);
                unsigned b1[2] = { Bs[kr][nc], Bs[kr + 4][nc] };
                mma_tf32(cO[0][nt], a[0], b1);
                mma_tf32(cO[1][nt], a[1], b1);
            }
        }
        __syncthreads();
    }

#pragma unroll
    for (int mt = 0; mt < 2; mt++) {
#pragma unroll
        for (int half = 0; half < 2; half++) {
            int r = wm + mt * 16 + (lane >> 2) + half * 8;
            if (m0 + r < cnt) {
                int rg = rloc[r];
                float wr = wloc[r];
                float* dst = g_slot + (size_t)rg * HH + n0 + wn;
#pragma unroll
                for (int nt = 0; nt < 4; nt++) {
                    float o0 = wr * cO[mt][nt][half * 2 + 0];
                    float o1 = wr * cO[mt][nt][half * 2 + 1];
                    int c = nt * 8 + (lane & 3) * 2;
                    *reinterpret_cast<float2*>(dst + c) = make_float2(o0, o1);
                }
            }
        }
    }
}

// ---------------- 4: combine the two expert slots per token ----------------
__global__ void combine_kernel(float* __restrict__ out) {
    int i = blockIdx.x * blockDim.x + threadIdx.x;   // float4 index
    const int n4 = TT * HH / 4;
    if (i >= n4) return;
    int t = i / (HH / 4);
    int h4 = i % (HH / 4);
    float4 a = reinterpret_cast<const float4*>(g_slot + (size_t)(2 * t) * HH)[h4];
    float4 b = reinterpret_cast<const float4*>(g_slot + (size_t)(2 * t + 1) * HH)[h4];
    float4 r = make_float4(a.x + b.x, a.y + b.y, a.z + b.z, a.w + b.w);
    reinterpret_cast<float4*>(out)[i] = r;
}

// ---------------- launch ----------------
extern "C" void kernel_launch(void* const* d_in, const int* in_sizes, int n_in,
                              void* d_out, int out_size) {
    (void)in_sizes; (void)n_in; (void)out_size;
    const float* x   = (const float*)d_in[0];
    const float* Wg  = (const float*)d_in[1];
    const float* W11 = (const float*)d_in[2];
    const float* W12 = (const float*)d_in[3];
    const float* W2  = (const float*)d_in[4];
    float* out = (float*)d_out;

    zero_cnt_kernel<<<1, 32>>>();
    router_kernel<<<TT / 4, 128>>>(x, Wg);                 // 4 warps/block

    dim3 g1(II / BN, TT / BM, EE);                         // (32, 64, 8)
    gemm1_kernel<<<g1, 128>>>(x, W11, W12);

    dim3 g2(HH / BN, TT / BM, EE);                         // (16, 64, 8)
    gemm2_kernel<<<g2, 128>>>(W2);

    combine_kernel<<<(TT * HH / 4 + 255) / 256, 256>>>(out);
}